// round 9
// baseline (speedup 1.0000x reference)
#include <cuda_runtime.h>

#define N_NODES 50000
#define N_EDGES 200000
#define OUTD 32
#define IN_SELF 128
#define EDGE_DIM 16

#define EB 296                 // edge jobs
#define SB 391                 // self/finish jobs = ceil(50000/128)
#define NJOBS (EB + SB)        // 687

#define BN 128
#define KB 32
#define BNP 132
#define NT 256

#define SCRATCH_FLOATS (N_NODES * OUTD + N_NODES)   // 1,650,000

__device__ float g_scratch[SCRATCH_FLOATS];
__device__ unsigned g_barrier_ctr;   // monotonic; never reset (graph-replay safe)

__device__ __forceinline__ void red_add_v4(float* ptr, float4 v) {
    asm volatile("red.global.add.v4.f32 [%0], {%1, %2, %3, %4};"
                 :: "l"(ptr), "f"(v.x), "f"(v.y), "f"(v.z), "f"(v.w)
                 : "memory");
}

__device__ __forceinline__ void fma2(unsigned long long& d,
                                     unsigned long long a,
                                     unsigned long long b) {
    asm("fma.rn.f32x2 %0, %1, %2, %0;" : "+l"(d) : "l"(a), "l"(b));
}

__device__ __forceinline__ unsigned long long packdup(float v) {
    unsigned long long r;
    asm("mov.b64 %0, {%1, %1};" : "=l"(r) : "f"(v));
    return r;
}

// Monotonic grid barrier: counter only grows; target derived from arrival
// ticket, so it needs no reset across graph replays.
__device__ __forceinline__ void grid_barrier(unsigned G) {
    __syncthreads();
    if (threadIdx.x == 0) {
        __threadfence();
        unsigned old = atomicAdd(&g_barrier_ctr, 1u);
        unsigned target = (old / G + 1u) * G;
        unsigned cur;
        do {
            asm volatile("ld.global.acquire.gpu.u32 %0, [%1];"
                         : "=r"(cur) : "l"(&g_barrier_ctr));
            if (cur >= target) break;
            __nanosleep(64);
        } while (true);
    }
    __syncthreads();
}

// ---------------------------------------------------------------------------
// Persistent kernel: phase0 zero -> phase1 [edge scatter || self-GEMM] ->
// phase2 finish. Grid sized from occupancy query (co-residency guaranteed).
// ---------------------------------------------------------------------------
__global__ void __launch_bounds__(NT, 3)
persistent_kernel(const float* __restrict__ h_neigh,
                  const float* __restrict__ h_self,
                  const float* __restrict__ edge_features,
                  const float* __restrict__ W_edge,
                  const float* __restrict__ b_edge,
                  const float* __restrict__ W_self,
                  const float* __restrict__ W_neigh,
                  const int* __restrict__ src,
                  const int* __restrict__ dst,
                  float* __restrict__ out) {
    __shared__ __align__(16) float smem_pool[10496];   // 42KB, unioned

    const unsigned G = gridDim.x;
    const int bid = blockIdx.x;
    const int t = threadIdx.x;

    float* g_agg = g_scratch;
    float* g_deg = g_scratch + N_NODES * OUTD;

    // ===================== PHASE 0: zero scratch =====================
    {
        float4* z = reinterpret_cast<float4*>(g_scratch);
        const int nz = SCRATCH_FLOATS / 4;   // 412500
        for (int i = bid * NT + t; i < nz; i += (int)G * NT)
            z[i] = make_float4(0.f, 0.f, 0.f, 0.f);
    }
    grid_barrier(G);

    // ===================== PHASE 1: edge || self =====================
    for (int j = bid; j < NJOBS; j += (int)G) {
        __syncthreads();   // previous job done with smem
        const bool is_edge = (j < 2 * EB) && ((j & 1) == 0);

        if (is_edge) {
            float* sW = smem_pool;          // [16][32]
            float* sb = smem_pool + 512;    // [32]
            for (int idx = t; idx < OUTD * EDGE_DIM; idx += NT) {
                int jj = idx >> 4, k = idx & 15;
                float s = 0.f;
                #pragma unroll
                for (int i = 0; i < OUTD; i++)
                    s += W_edge[(i * OUTD + jj) * EDGE_DIM + k];
                sW[k * OUTD + jj] = s;
            }
            if (t < OUTD) {
                float s2 = 0.f;
                #pragma unroll
                for (int i = 0; i < OUTD; i++)
                    s2 += b_edge[i * OUTD + t];
                sb[t] = s2;
            }
            __syncthreads();

            const int eid = j >> 1;
            const int lane = t & 31;
            const int warp = t >> 5;
            const int g = lane >> 3;
            const int p = lane & 7;
            const int wpb = NT >> 5;           // 8
            const int nwarps = EB * wpb;       // 2368
            const int NGROUPS = N_EDGES / 4;   // 50000

            for (int grp = eid * wpb + warp; grp < NGROUPS; grp += nwarps) {
                int e0 = grp * 4;
                int e = e0 + g;
                int s = src[e];
                int d = dst[e];

                float2 ef = *reinterpret_cast<const float2*>(
                    &edge_features[e0 * EDGE_DIM + lane * 2]);

                float4 acc = *reinterpret_cast<const float4*>(&sb[4 * p]);
                #pragma unroll
                for (int k = 0; k < EDGE_DIM; k++) {
                    float ek = __shfl_sync(0xffffffffu, (k & 1) ? ef.y : ef.x, k >> 1, 8);
                    float4 w = *reinterpret_cast<const float4*>(&sW[k * OUTD + 4 * p]);
                    acc.x = fmaf(ek, w.x, acc.x);
                    acc.y = fmaf(ek, w.y, acc.y);
                    acc.z = fmaf(ek, w.z, acc.z);
                    acc.w = fmaf(ek, w.w, acc.w);
                }

                float4 hv = *reinterpret_cast<const float4*>(&h_neigh[s * OUTD + 4 * p]);
                float4 msg = make_float4(hv.x * acc.x, hv.y * acc.y,
                                         hv.z * acc.z, hv.w * acc.w);
                red_add_v4(&g_agg[d * OUTD + 4 * p], msg);
                if (p == 0) atomicAdd(&g_deg[d], 1.0f);
            }
        } else {
            const int sid = (j < 2 * EB) ? (j >> 1) : (j - EB);
            float (*h_s)[KB][BNP] = reinterpret_cast<float(*)[KB][BNP]>(smem_pool);
            float (*w_s)[KB][OUTD] = reinterpret_cast<float(*)[KB][OUTD]>(smem_pool + 8448);

            const int nbase = sid * BN;
            const int kg = t >> 7;
            const int t1 = t & 127;
            const int tn = t1 >> 3;
            const int tc = t1 & 7;
            const int ko = kg * (KB / 2);

            const int snode = t >> 3;
            const int skvec = t & 7;
            const int wchan = t >> 3;
            const int wkvec = t & 7;

            float4 hreg[4];
            float4 wreg;

            auto load_regs = [&](int kc) {
                #pragma unroll
                for (int i = 0; i < 4; i++) {
                    int node = snode + i * (NT >> 3);
                    int gn = nbase + node;
                    float4 v = make_float4(0.f, 0.f, 0.f, 0.f);
                    if (gn < N_NODES)
                        v = *reinterpret_cast<const float4*>(
                            &h_self[gn * IN_SELF + kc * KB + skvec * 4]);
                    hreg[i] = v;
                }
                wreg = *reinterpret_cast<const float4*>(
                    &W_self[wchan * IN_SELF + kc * KB + wkvec * 4]);
            };

            auto store_smem = [&](int b) {
                #pragma unroll
                for (int i = 0; i < 4; i++) {
                    int node = snode + i * (NT >> 3);
                    h_s[b][skvec * 4 + 0][node] = hreg[i].x;
                    h_s[b][skvec * 4 + 1][node] = hreg[i].y;
                    h_s[b][skvec * 4 + 2][node] = hreg[i].z;
                    h_s[b][skvec * 4 + 3][node] = hreg[i].w;
                }
                w_s[b][wkvec * 4 + 0][wchan] = wreg.x;
                w_s[b][wkvec * 4 + 1][wchan] = wreg.y;
                w_s[b][wkvec * 4 + 2][wchan] = wreg.z;
                w_s[b][wkvec * 4 + 3][wchan] = wreg.w;
            };

            unsigned long long acc2[4][4];
            #pragma unroll
            for (int p = 0; p < 4; p++)
                #pragma unroll
                for (int c = 0; c < 4; c++) acc2[p][c] = 0ull;

            load_regs(0);
            store_smem(0);
            __syncthreads();

            #pragma unroll
            for (int kc = 0; kc < 4; kc++) {
                int b = kc & 1;
                if (kc < 3) load_regs(kc + 1);
                #pragma unroll
                for (int kk = 0; kk < KB / 2; kk++) {
                    int k = kk + ko;
                    float4 w = *reinterpret_cast<const float4*>(&w_s[b][k][tc * 4]);
                    unsigned long long w0 = packdup(w.x);
                    unsigned long long w1 = packdup(w.y);
                    unsigned long long w2 = packdup(w.z);
                    unsigned long long w3 = packdup(w.w);
                    ulonglong2 hA = *reinterpret_cast<const ulonglong2*>(&h_s[b][k][tn * 8]);
                    ulonglong2 hB = *reinterpret_cast<const ulonglong2*>(&h_s[b][k][tn * 8 + 4]);

                    fma2(acc2[0][0], hA.x, w0);
                    fma2(acc2[0][1], hA.x, w1);
                    fma2(acc2[0][2], hA.x, w2);
                    fma2(acc2[0][3], hA.x, w3);
                    fma2(acc2[1][0], hA.y, w0);
                    fma2(acc2[1][1], hA.y, w1);
                    fma2(acc2[1][2], hA.y, w2);
                    fma2(acc2[1][3], hA.y, w3);
                    fma2(acc2[2][0], hB.x, w0);
                    fma2(acc2[2][1], hB.x, w1);
                    fma2(acc2[2][2], hB.x, w2);
                    fma2(acc2[2][3], hB.x, w3);
                    fma2(acc2[3][0], hB.y, w0);
                    fma2(acc2[3][1], hB.y, w1);
                    fma2(acc2[3][2], hB.y, w2);
                    fma2(acc2[3][3], hB.y, w3);
                }
                if (kc < 3) store_smem(1 - b);
                __syncthreads();
            }

            unsigned long long* red = reinterpret_cast<unsigned long long*>(smem_pool);
            if (kg == 1) {
                #pragma unroll
                for (int p = 0; p < 4; p++)
                    #pragma unroll
                    for (int c = 0; c < 4; c++)
                        red[t1 * 16 + p * 4 + c] = acc2[p][c];
            }
            __syncthreads();
            if (kg == 0) {
                #pragma unroll
                for (int p = 0; p < 4; p++) {
                    float lo[4], hi[4];
                    #pragma unroll
                    for (int c = 0; c < 4; c++) {
                        float2 a = *reinterpret_cast<float2*>(&acc2[p][c]);
                        unsigned long long o = red[t1 * 16 + p * 4 + c];
                        float2 bq = *reinterpret_cast<float2*>(&o);
                        lo[c] = a.x + bq.x;
                        hi[c] = a.y + bq.y;
                    }
                    int gn0 = nbase + tn * 8 + 2 * p;
                    if (gn0 < N_NODES)
                        *reinterpret_cast<float4*>(&out[gn0 * OUTD + tc * 4]) =
                            make_float4(lo[0], lo[1], lo[2], lo[3]);
                    if (gn0 + 1 < N_NODES)
                        *reinterpret_cast<float4*>(&out[(gn0 + 1) * OUTD + tc * 4]) =
                            make_float4(hi[0], hi[1], hi[2], hi[3]);
                }
            }
        }
    }
    grid_barrier(G);

    // ===================== PHASE 2: finish =====================
    for (int j = bid; j < SB; j += (int)G) {
        __syncthreads();
        float (*a_s)[BNP] = reinterpret_cast<float(*)[BNP]>(smem_pool);         // [32][132]
        float (*w2)[OUTD] = reinterpret_cast<float(*)[OUTD]>(smem_pool + 4224); // [32][32]
        float* sinv = smem_pool + 5248;                                          // [128]

        const int nbase = j * BN;
        const int tn = t >> 3;
        const int tc = t & 7;

        if (t < BN) {
            int gn = nbase + t;
            sinv[t] = (gn < N_NODES) ? 1.0f / fmaxf(g_deg[gn], 1.0f) : 0.f;
        }
        __syncthreads();

        #pragma unroll
        for (int i = 0; i < 4; i++) {
            int idx = t + i * NT;
            int node = idx >> 3;
            int kvec = idx & 7;
            int gn = nbase + node;
            float4 v = make_float4(0.f, 0.f, 0.f, 0.f);
            if (gn < N_NODES) {
                v = *reinterpret_cast<const float4*>(&g_agg[gn * OUTD + kvec * 4]);
                float iv = sinv[node];
                v.x *= iv; v.y *= iv; v.z *= iv; v.w *= iv;
            }
            a_s[kvec * 4 + 0][node] = v.x;
            a_s[kvec * 4 + 1][node] = v.y;
            a_s[kvec * 4 + 2][node] = v.z;
            a_s[kvec * 4 + 3][node] = v.w;
        }
        {
            int chan = t >> 3, kvec = t & 7;
            float4 w = *reinterpret_cast<const float4*>(&W_neigh[chan * OUTD + kvec * 4]);
            w2[kvec * 4 + 0][chan] = w.x;
            w2[kvec * 4 + 1][chan] = w.y;
            w2[kvec * 4 + 2][chan] = w.z;
            w2[kvec * 4 + 3][chan] = w.w;
        }
        __syncthreads();

        float acc[4][4];
        #pragma unroll
        for (int r = 0; r < 4; r++) {
            int gn = nbase + tn * 4 + r;
            float4 s = make_float4(0.f, 0.f, 0.f, 0.f);
            if (gn < N_NODES)
                s = *reinterpret_cast<const float4*>(&out[gn * OUTD + tc * 4]);
            acc[r][0] = s.x; acc[r][1] = s.y; acc[r][2] = s.z; acc[r][3] = s.w;
        }

        #pragma unroll
        for (int kk = 0; kk < KB; kk++) {
            float4 w = *reinterpret_cast<const float4*>(&w2[kk][tc * 4]);
            float4 h = *reinterpret_cast<const float4*>(&a_s[kk][tn * 4]);
            float hr[4] = {h.x, h.y, h.z, h.w};
            float wc[4] = {w.x, w.y, w.z, w.w};
            #pragma unroll
            for (int r = 0; r < 4; r++)
                #pragma unroll
                for (int c = 0; c < 4; c++)
                    acc[r][c] = fmaf(hr[r], wc[c], acc[r][c]);
        }

        #pragma unroll
        for (int r = 0; r < 4; r++) {
            int gn = nbase + tn * 4 + r;
            if (gn < N_NODES) {
                float4 o = make_float4(fmaxf(acc[r][0], 0.f), fmaxf(acc[r][1], 0.f),
                                       fmaxf(acc[r][2], 0.f), fmaxf(acc[r][3], 0.f));
                *reinterpret_cast<float4*>(&out[gn * OUTD + tc * 4]) = o;
            }
        }
    }
}

extern "C" void kernel_launch(void* const* d_in, const int* in_sizes, int n_in,
                              void* d_out, int out_size) {
    const float* h_neigh       = (const float*)d_in[0];
    const float* h_self        = (const float*)d_in[1];
    const float* edge_features = (const float*)d_in[2];
    const float* W_edge        = (const float*)d_in[3];
    const float* b_edge        = (const float*)d_in[4];
    const float* W_self        = (const float*)d_in[5];
    const float* W_neigh       = (const float*)d_in[6];
    const int*   src           = (const int*)d_in[7];
    const int*   dst           = (const int*)d_in[8];
    float* out = (float*)d_out;

    // Co-residency-safe persistent grid: query real occupancy (deterministic).
    int dev = 0, sms = 0, occ = 0;
    cudaGetDevice(&dev);
    cudaDeviceGetAttribute(&sms, cudaDevAttrMultiProcessorCount, dev);
    cudaOccupancyMaxActiveBlocksPerMultiprocessor(&occ, persistent_kernel, NT, 0);
    if (occ < 1) occ = 1;
    int grid = sms * occ;
    if (grid > NJOBS) grid = NJOBS;

    persistent_kernel<<<grid, NT>>>(h_neigh, h_self, edge_features,
                                    W_edge, b_edge, W_self, W_neigh,
                                    src, dst, out);
}

// round 10
// speedup vs baseline: 1.3846x; 1.3846x over previous
#include <cuda_runtime.h>

#define N_NODES 50000
#define N_EDGES 200000
#define OUTD 32
#define IN_SELF 128
#define EDGE_DIM 16

#define EDGE_BLOCKS 592
#define EDGE_THREADS 256

#define BN 128
#define KB 32
#define BNP 132
#define NT 256
#define SB 391

__device__ float g_scratch[N_NODES * OUTD + N_NODES];

__device__ __forceinline__ void red_add_v4(float* ptr, float4 v) {
    asm volatile("red.global.add.v4.f32 [%0], {%1, %2, %3, %4};"
                 :: "l"(ptr), "f"(v.x), "f"(v.y), "f"(v.z), "f"(v.w)
                 : "memory");
}

__device__ __forceinline__ void fma2(unsigned long long& d,
                                     unsigned long long a,
                                     unsigned long long b) {
    asm("fma.rn.f32x2 %0, %1, %2, %0;" : "+l"(d) : "l"(a), "l"(b));
}

__device__ __forceinline__ unsigned long long packdup(float v) {
    unsigned long long r;
    asm("mov.b64 %0, {%1, %1};" : "=l"(r) : "f"(v));
    return r;
}

// ---------------------------------------------------------------------------
// Edge kernel: software-pipelined scatter.
// 4 edges per warp (8 lanes/edge, 4 chans/lane). Depth-2 pipeline: next
// group's src/dst/ef prefetched during current colsum; h load issued before
// the shfl chain so its L2 latency overlaps compute.
// ---------------------------------------------------------------------------
__global__ void __launch_bounds__(EDGE_THREADS)
edge_kernel(const float* __restrict__ h_neigh,
            const float* __restrict__ edge_features,
            const float* __restrict__ W_edge,
            const float* __restrict__ b_edge,
            const int* __restrict__ src,
            const int* __restrict__ dst) {
    __shared__ __align__(16) float sW[EDGE_DIM * OUTD];
    __shared__ __align__(16) float sb[OUTD];
    {
        for (int idx = threadIdx.x; idx < OUTD * EDGE_DIM; idx += EDGE_THREADS) {
            int j = idx >> 4, k = idx & 15;
            float s = 0.f;
            #pragma unroll
            for (int i = 0; i < OUTD; i++)
                s += W_edge[(i * OUTD + j) * EDGE_DIM + k];
            sW[k * OUTD + j] = s;
        }
        if (threadIdx.x < OUTD) {
            float s2 = 0.f;
            #pragma unroll
            for (int i = 0; i < OUTD; i++)
                s2 += b_edge[i * OUTD + threadIdx.x];
            sb[threadIdx.x] = s2;
        }
    }
    __syncthreads();

    float* g_agg = g_scratch;
    float* g_deg = g_scratch + N_NODES * OUTD;

    const int lane = threadIdx.x & 31;
    const int warp = threadIdx.x >> 5;
    const int g = lane >> 3;
    const int p = lane & 7;
    const int wpb = EDGE_THREADS >> 5;            // 8
    const int nwarps = EDGE_BLOCKS * wpb;         // 4736
    const int NGROUPS = N_EDGES / 4;              // 50000

    const float4 biasv = *reinterpret_cast<const float4*>(&sb[4 * p]);

    int grp = blockIdx.x * wpb + warp;
    if (grp >= NGROUPS) return;

    // prologue: load group 0 state
    int s = src[grp * 4 + g];
    int d = dst[grp * 4 + g];
    float2 ef = *reinterpret_cast<const float2*>(
        &edge_features[grp * 4 * EDGE_DIM + lane * 2]);

    #pragma unroll 1
    while (true) {
        // issue h load early (L2 latency overlaps the shfl/FMA chain below)
        float4 hv = *reinterpret_cast<const float4*>(&h_neigh[s * OUTD + 4 * p]);

        // prefetch next group's indices + edge features
        int next = grp + nwarps;
        int s2 = 0, d2 = 0;
        float2 ef2 = make_float2(0.f, 0.f);
        bool more = (next < NGROUPS);
        if (more) {
            s2 = src[next * 4 + g];
            d2 = dst[next * 4 + g];
            ef2 = *reinterpret_cast<const float2*>(
                &edge_features[next * 4 * EDGE_DIM + lane * 2]);
        }

        // colsum for current group
        float4 acc = biasv;
        #pragma unroll
        for (int k = 0; k < EDGE_DIM; k++) {
            float ek = __shfl_sync(0xffffffffu, (k & 1) ? ef.y : ef.x, k >> 1, 8);
            float4 w = *reinterpret_cast<const float4*>(&sW[k * OUTD + 4 * p]);
            acc.x = fmaf(ek, w.x, acc.x);
            acc.y = fmaf(ek, w.y, acc.y);
            acc.z = fmaf(ek, w.z, acc.z);
            acc.w = fmaf(ek, w.w, acc.w);
        }

        float4 msg = make_float4(hv.x * acc.x, hv.y * acc.y,
                                 hv.z * acc.z, hv.w * acc.w);
        red_add_v4(&g_agg[d * OUTD + 4 * p], msg);
        if (p == 0) atomicAdd(&g_deg[d], 1.0f);

        if (!more) break;
        s = s2; d = d2; ef = ef2; grp = next;
    }
}

// ---------------------------------------------------------------------------
// Node kernel (R7 verbatim — proven 23.6us): split-K f32x2 GEMM.
//   out[n,c] = relu( X[n,:] . Wc[c,:] ),  X=[h_self | agg/deg], K=160.
// ---------------------------------------------------------------------------
__global__ void __launch_bounds__(NT, 3)
node_kernel(const float* __restrict__ h_self,
            const float* __restrict__ W_self,
            const float* __restrict__ W_neigh,
            float* __restrict__ out) {
    __shared__ __align__(16) float h_s[2][KB][BNP];
    __shared__ __align__(16) float w_s[2][KB][OUTD];
    __shared__ float sinv[BN];

    const float* g_agg = g_scratch;
    const float* g_deg = g_scratch + N_NODES * OUTD;

    const int t = threadIdx.x;
    const int nbase = blockIdx.x * BN;
    const int kg = t >> 7;
    const int t1 = t & 127;
    const int tn = t1 >> 3;
    const int tc = t1 & 7;
    const int ko = kg * (KB / 2);

    const int snode = t >> 3;
    const int skvec = t & 7;
    const int wchan = t >> 3;
    const int wkvec = t & 7;

    if (t < BN) {
        int gn = nbase + t;
        sinv[t] = (gn < N_NODES) ? 1.0f / fmaxf(g_deg[gn], 1.0f) : 0.f;
    }

    float4 hreg[4];
    float4 wreg;

    auto load_regs = [&](int kc) {
        #pragma unroll
        for (int i = 0; i < 4; i++) {
            int node = snode + i * (NT >> 3);
            int gn = nbase + node;
            float4 v = make_float4(0.f, 0.f, 0.f, 0.f);
            if (gn < N_NODES) {
                if (kc < 4) {
                    v = *reinterpret_cast<const float4*>(
                        &h_self[gn * IN_SELF + kc * KB + skvec * 4]);
                } else {
                    v = *reinterpret_cast<const float4*>(
                        &g_agg[gn * OUTD + skvec * 4]);
                    float iv = sinv[node];
                    v.x *= iv; v.y *= iv; v.z *= iv; v.w *= iv;
                }
            }
            hreg[i] = v;
        }
        if (kc < 4)
            wreg = *reinterpret_cast<const float4*>(
                &W_self[wchan * IN_SELF + kc * KB + wkvec * 4]);
        else
            wreg = *reinterpret_cast<const float4*>(
                &W_neigh[wchan * OUTD + wkvec * 4]);
    };

    auto store_smem = [&](int b) {
        #pragma unroll
        for (int i = 0; i < 4; i++) {
            int node = snode + i * (NT >> 3);
            h_s[b][skvec * 4 + 0][node] = hreg[i].x;
            h_s[b][skvec * 4 + 1][node] = hreg[i].y;
            h_s[b][skvec * 4 + 2][node] = hreg[i].z;
            h_s[b][skvec * 4 + 3][node] = hreg[i].w;
        }
        w_s[b][wkvec * 4 + 0][wchan] = wreg.x;
        w_s[b][wkvec * 4 + 1][wchan] = wreg.y;
        w_s[b][wkvec * 4 + 2][wchan] = wreg.z;
        w_s[b][wkvec * 4 + 3][wchan] = wreg.w;
    };

    unsigned long long acc2[4][4];
    #pragma unroll
    for (int p = 0; p < 4; p++)
        #pragma unroll
        for (int c = 0; c < 4; c++) acc2[p][c] = 0ull;

    load_regs(0);
    __syncthreads();      // sinv visible, smem free
    store_smem(0);
    __syncthreads();

    #pragma unroll
    for (int kc = 0; kc < 5; kc++) {
        int b = kc & 1;
        if (kc < 4) load_regs(kc + 1);
        #pragma unroll
        for (int kk = 0; kk < KB / 2; kk++) {
            int k = kk + ko;
            float4 w = *reinterpret_cast<const float4*>(&w_s[b][k][tc * 4]);
            unsigned long long w0 = packdup(w.x);
            unsigned long long w1 = packdup(w.y);
            unsigned long long w2 = packdup(w.z);
            unsigned long long w3 = packdup(w.w);
            ulonglong2 hA = *reinterpret_cast<const ulonglong2*>(&h_s[b][k][tn * 8]);
            ulonglong2 hB = *reinterpret_cast<const ulonglong2*>(&h_s[b][k][tn * 8 + 4]);

            fma2(acc2[0][0], hA.x, w0);
            fma2(acc2[0][1], hA.x, w1);
            fma2(acc2[0][2], hA.x, w2);
            fma2(acc2[0][3], hA.x, w3);
            fma2(acc2[1][0], hA.y, w0);
            fma2(acc2[1][1], hA.y, w1);
            fma2(acc2[1][2], hA.y, w2);
            fma2(acc2[1][3], hA.y, w3);
            fma2(acc2[2][0], hB.x, w0);
            fma2(acc2[2][1], hB.x, w1);
            fma2(acc2[2][2], hB.x, w2);
            fma2(acc2[2][3], hB.x, w3);
            fma2(acc2[3][0], hB.y, w0);
            fma2(acc2[3][1], hB.y, w1);
            fma2(acc2[3][2], hB.y, w2);
            fma2(acc2[3][3], hB.y, w3);
        }
        if (kc < 4) store_smem(1 - b);
        __syncthreads();
    }

    unsigned long long* red = reinterpret_cast<unsigned long long*>(h_s);
    if (kg == 1) {
        #pragma unroll
        for (int p = 0; p < 4; p++)
            #pragma unroll
            for (int c = 0; c < 4; c++)
                red[t1 * 16 + p * 4 + c] = acc2[p][c];
    }
    __syncthreads();
    if (kg == 0) {
        #pragma unroll
        for (int p = 0; p < 4; p++) {
            float lo[4], hi[4];
            #pragma unroll
            for (int c = 0; c < 4; c++) {
                float2 a = *reinterpret_cast<float2*>(&acc2[p][c]);
                unsigned long long o = red[t1 * 16 + p * 4 + c];
                float2 bq = *reinterpret_cast<float2*>(&o);
                lo[c] = fmaxf(a.x + bq.x, 0.f);
                hi[c] = fmaxf(a.y + bq.y, 0.f);
            }
            int gn0 = nbase + tn * 8 + 2 * p;
            if (gn0 < N_NODES)
                *reinterpret_cast<float4*>(&out[gn0 * OUTD + tc * 4]) =
                    make_float4(lo[0], lo[1], lo[2], lo[3]);
            if (gn0 + 1 < N_NODES)
                *reinterpret_cast<float4*>(&out[(gn0 + 1) * OUTD + tc * 4]) =
                    make_float4(hi[0], hi[1], hi[2], hi[3]);
        }
    }
}

extern "C" void kernel_launch(void* const* d_in, const int* in_sizes, int n_in,
                              void* d_out, int out_size) {
    const float* h_neigh       = (const float*)d_in[0];
    const float* h_self        = (const float*)d_in[1];
    const float* edge_features = (const float*)d_in[2];
    const float* W_edge        = (const float*)d_in[3];
    const float* b_edge        = (const float*)d_in[4];
    const float* W_self        = (const float*)d_in[5];
    const float* W_neigh       = (const float*)d_in[6];
    const int*   src           = (const int*)d_in[7];
    const int*   dst           = (const int*)d_in[8];
    float* out = (float*)d_out;

    void* scratch_ptr = nullptr;
    cudaGetSymbolAddress(&scratch_ptr, g_scratch);
    cudaMemsetAsync(scratch_ptr, 0, sizeof(float) * (N_NODES * OUTD + N_NODES), 0);

    edge_kernel<<<EDGE_BLOCKS, EDGE_THREADS>>>(h_neigh, edge_features,
                                               W_edge, b_edge, src, dst);
    node_kernel<<<SB, NT>>>(h_self, W_self, W_neigh, out);
}

// round 11
// speedup vs baseline: 1.4416x; 1.0412x over previous
#include <cuda_runtime.h>

#define N_NODES 50000
#define N_EDGES 200000
#define OUTD 32
#define IN_SELF 128
#define EDGE_DIM 16

#define EDGE_BLOCKS 592
#define EDGE_THREADS 256

#define BN 128
#define KB 32
#define BNP 132
#define NT 256
#define SB 391

// Zero-initialized at module load; node_kernel re-zeroes after consuming,
// so the zero-invariant holds across graph replays with NO memset launch.
__device__ float g_scratch[N_NODES * OUTD + N_NODES];

__device__ __forceinline__ void red_add_v4(float* ptr, float4 v) {
    asm volatile("red.global.add.v4.f32 [%0], {%1, %2, %3, %4};"
                 :: "l"(ptr), "f"(v.x), "f"(v.y), "f"(v.z), "f"(v.w)
                 : "memory");
}

__device__ __forceinline__ void fma2(unsigned long long& d,
                                     unsigned long long a,
                                     unsigned long long b) {
    asm("fma.rn.f32x2 %0, %1, %2, %0;" : "+l"(d) : "l"(a), "l"(b));
}

__device__ __forceinline__ unsigned long long packdup(float v) {
    unsigned long long r;
    asm("mov.b64 %0, {%1, %1};" : "=l"(r) : "f"(v));
    return r;
}

// ---------------------------------------------------------------------------
// Edge kernel (R10 verbatim): software-pipelined scatter.
// ---------------------------------------------------------------------------
__global__ void __launch_bounds__(EDGE_THREADS)
edge_kernel(const float* __restrict__ h_neigh,
            const float* __restrict__ edge_features,
            const float* __restrict__ W_edge,
            const float* __restrict__ b_edge,
            const int* __restrict__ src,
            const int* __restrict__ dst) {
    __shared__ __align__(16) float sW[EDGE_DIM * OUTD];
    __shared__ __align__(16) float sb[OUTD];
    {
        for (int idx = threadIdx.x; idx < OUTD * EDGE_DIM; idx += EDGE_THREADS) {
            int j = idx >> 4, k = idx & 15;
            float s = 0.f;
            #pragma unroll
            for (int i = 0; i < OUTD; i++)
                s += W_edge[(i * OUTD + j) * EDGE_DIM + k];
            sW[k * OUTD + j] = s;
        }
        if (threadIdx.x < OUTD) {
            float s2 = 0.f;
            #pragma unroll
            for (int i = 0; i < OUTD; i++)
                s2 += b_edge[i * OUTD + threadIdx.x];
            sb[threadIdx.x] = s2;
        }
    }
    __syncthreads();

    float* g_agg = g_scratch;
    float* g_deg = g_scratch + N_NODES * OUTD;

    const int lane = threadIdx.x & 31;
    const int warp = threadIdx.x >> 5;
    const int g = lane >> 3;
    const int p = lane & 7;
    const int wpb = EDGE_THREADS >> 5;
    const int nwarps = EDGE_BLOCKS * wpb;       // 4736
    const int NGROUPS = N_EDGES / 4;            // 50000

    const float4 biasv = *reinterpret_cast<const float4*>(&sb[4 * p]);

    int grp = blockIdx.x * wpb + warp;
    if (grp >= NGROUPS) return;

    int s = src[grp * 4 + g];
    int d = dst[grp * 4 + g];
    float2 ef = *reinterpret_cast<const float2*>(
        &edge_features[grp * 4 * EDGE_DIM + lane * 2]);

    #pragma unroll 1
    while (true) {
        float4 hv = *reinterpret_cast<const float4*>(&h_neigh[s * OUTD + 4 * p]);

        int next = grp + nwarps;
        int s2 = 0, d2 = 0;
        float2 ef2 = make_float2(0.f, 0.f);
        bool more = (next < NGROUPS);
        if (more) {
            s2 = src[next * 4 + g];
            d2 = dst[next * 4 + g];
            ef2 = *reinterpret_cast<const float2*>(
                &edge_features[next * 4 * EDGE_DIM + lane * 2]);
        }

        float4 acc = biasv;
        #pragma unroll
        for (int k = 0; k < EDGE_DIM; k++) {
            float ek = __shfl_sync(0xffffffffu, (k & 1) ? ef.y : ef.x, k >> 1, 8);
            float4 w = *reinterpret_cast<const float4*>(&sW[k * OUTD + 4 * p]);
            acc.x = fmaf(ek, w.x, acc.x);
            acc.y = fmaf(ek, w.y, acc.y);
            acc.z = fmaf(ek, w.z, acc.z);
            acc.w = fmaf(ek, w.w, acc.w);
        }

        float4 msg = make_float4(hv.x * acc.x, hv.y * acc.y,
                                 hv.z * acc.z, hv.w * acc.w);
        red_add_v4(&g_agg[d * OUTD + 4 * p], msg);
        if (p == 0) atomicAdd(&g_deg[d], 1.0f);

        if (!more) break;
        s = s2; d = d2; ef = ef2; grp = next;
    }
}

// ---------------------------------------------------------------------------
// Node kernel: split-K f32x2 GEMM (R7 proven) + self-cleaning scratch:
// agg is zeroed as it is staged (read-once), deg zeroed as sinv is built.
// ---------------------------------------------------------------------------
__global__ void __launch_bounds__(NT, 3)
node_kernel(const float* __restrict__ h_self,
            const float* __restrict__ W_self,
            const float* __restrict__ W_neigh,
            float* __restrict__ out) {
    __shared__ __align__(16) float h_s[2][KB][BNP];
    __shared__ __align__(16) float w_s[2][KB][OUTD];
    __shared__ float sinv[BN];

    float* g_agg = g_scratch;                    // non-const: we zero it
    float* g_deg = g_scratch + N_NODES * OUTD;

    const int t = threadIdx.x;
    const int nbase = blockIdx.x * BN;
    const int kg = t >> 7;
    const int t1 = t & 127;
    const int tn = t1 >> 3;
    const int tc = t1 & 7;
    const int ko = kg * (KB / 2);

    const int snode = t >> 3;
    const int skvec = t & 7;
    const int wchan = t >> 3;
    const int wkvec = t & 7;

    if (t < BN) {
        int gn = nbase + t;
        if (gn < N_NODES) {
            float dv = g_deg[gn];
            g_deg[gn] = 0.f;                     // self-clean deg
            sinv[t] = 1.0f / fmaxf(dv, 1.0f);
        } else {
            sinv[t] = 0.f;
        }
    }

    float4 hreg[4];
    float4 wreg;

    auto load_regs = [&](int kc) {
        #pragma unroll
        for (int i = 0; i < 4; i++) {
            int node = snode + i * (NT >> 3);
            int gn = nbase + node;
            float4 v = make_float4(0.f, 0.f, 0.f, 0.f);
            if (gn < N_NODES) {
                if (kc < 4) {
                    v = *reinterpret_cast<const float4*>(
                        &h_self[gn * IN_SELF + kc * KB + skvec * 4]);
                } else {
                    float4* ap = reinterpret_cast<float4*>(
                        &g_agg[gn * OUTD + skvec * 4]);
                    v = *ap;
                    *ap = make_float4(0.f, 0.f, 0.f, 0.f);  // self-clean agg
                    float iv = sinv[node];
                    v.x *= iv; v.y *= iv; v.z *= iv; v.w *= iv;
                }
            }
            hreg[i] = v;
        }
        if (kc < 4)
            wreg = *reinterpret_cast<const float4*>(
                &W_self[wchan * IN_SELF + kc * KB + wkvec * 4]);
        else
            wreg = *reinterpret_cast<const float4*>(
                &W_neigh[wchan * OUTD + wkvec * 4]);
    };

    auto store_smem = [&](int b) {
        #pragma unroll
        for (int i = 0; i < 4; i++) {
            int node = snode + i * (NT >> 3);
            h_s[b][skvec * 4 + 0][node] = hreg[i].x;
            h_s[b][skvec * 4 + 1][node] = hreg[i].y;
            h_s[b][skvec * 4 + 2][node] = hreg[i].z;
            h_s[b][skvec * 4 + 3][node] = hreg[i].w;
        }
        w_s[b][wkvec * 4 + 0][wchan] = wreg.x;
        w_s[b][wkvec * 4 + 1][wchan] = wreg.y;
        w_s[b][wkvec * 4 + 2][wchan] = wreg.z;
        w_s[b][wkvec * 4 + 3][wchan] = wreg.w;
    };

    unsigned long long acc2[4][4];
    #pragma unroll
    for (int p = 0; p < 4; p++)
        #pragma unroll
        for (int c = 0; c < 4; c++) acc2[p][c] = 0ull;

    load_regs(0);
    __syncthreads();      // sinv visible, smem free
    store_smem(0);
    __syncthreads();

    #pragma unroll
    for (int kc = 0; kc < 5; kc++) {
        int b = kc & 1;
        if (kc < 4) load_regs(kc + 1);
        #pragma unroll
        for (int kk = 0; kk < KB / 2; kk++) {
            int k = kk + ko;
            float4 w = *reinterpret_cast<const float4*>(&w_s[b][k][tc * 4]);
            unsigned long long w0 = packdup(w.x);
            unsigned long long w1 = packdup(w.y);
            unsigned long long w2 = packdup(w.z);
            unsigned long long w3 = packdup(w.w);
            ulonglong2 hA = *reinterpret_cast<const ulonglong2*>(&h_s[b][k][tn * 8]);
            ulonglong2 hB = *reinterpret_cast<const ulonglong2*>(&h_s[b][k][tn * 8 + 4]);

            fma2(acc2[0][0], hA.x, w0);
            fma2(acc2[0][1], hA.x, w1);
            fma2(acc2[0][2], hA.x, w2);
            fma2(acc2[0][3], hA.x, w3);
            fma2(acc2[1][0], hA.y, w0);
            fma2(acc2[1][1], hA.y, w1);
            fma2(acc2[1][2], hA.y, w2);
            fma2(acc2[1][3], hA.y, w3);
            fma2(acc2[2][0], hB.x, w0);
            fma2(acc2[2][1], hB.x, w1);
            fma2(acc2[2][2], hB.x, w2);
            fma2(acc2[2][3], hB.x, w3);
            fma2(acc2[3][0], hB.y, w0);
            fma2(acc2[3][1], hB.y, w1);
            fma2(acc2[3][2], hB.y, w2);
            fma2(acc2[3][3], hB.y, w3);
        }
        if (kc < 4) store_smem(1 - b);
        __syncthreads();
    }

    unsigned long long* red = reinterpret_cast<unsigned long long*>(h_s);
    if (kg == 1) {
        #pragma unroll
        for (int p = 0; p < 4; p++)
            #pragma unroll
            for (int c = 0; c < 4; c++)
                red[t1 * 16 + p * 4 + c] = acc2[p][c];
    }
    __syncthreads();
    if (kg == 0) {
        #pragma unroll
        for (int p = 0; p < 4; p++) {
            float lo[4], hi[4];
            #pragma unroll
            for (int c = 0; c < 4; c++) {
                float2 a = *reinterpret_cast<float2*>(&acc2[p][c]);
                unsigned long long o = red[t1 * 16 + p * 4 + c];
                float2 bq = *reinterpret_cast<float2*>(&o);
                lo[c] = fmaxf(a.x + bq.x, 0.f);
                hi[c] = fmaxf(a.y + bq.y, 0.f);
            }
            int gn0 = nbase + tn * 8 + 2 * p;
            if (gn0 < N_NODES)
                *reinterpret_cast<float4*>(&out[gn0 * OUTD + tc * 4]) =
                    make_float4(lo[0], lo[1], lo[2], lo[3]);
            if (gn0 + 1 < N_NODES)
                *reinterpret_cast<float4*>(&out[(gn0 + 1) * OUTD + tc * 4]) =
                    make_float4(hi[0], hi[1], hi[2], hi[3]);
        }
    }
}

extern "C" void kernel_launch(void* const* d_in, const int* in_sizes, int n_in,
                              void* d_out, int out_size) {
    const float* h_neigh       = (const float*)d_in[0];
    const float* h_self        = (const float*)d_in[1];
    const float* edge_features = (const float*)d_in[2];
    const float* W_edge        = (const float*)d_in[3];
    const float* b_edge        = (const float*)d_in[4];
    const float* W_self        = (const float*)d_in[5];
    const float* W_neigh       = (const float*)d_in[6];
    const int*   src           = (const int*)d_in[7];
    const int*   dst           = (const int*)d_in[8];
    float* out = (float*)d_out;

    // No memset: g_scratch starts zeroed (module load) and node_kernel
    // re-zeroes agg/deg as it consumes them, preserving the invariant
    // across graph replays. Two launches total.
    edge_kernel<<<EDGE_BLOCKS, EDGE_THREADS>>>(h_neigh, edge_features,
                                               W_edge, b_edge, src, dst);
    node_kernel<<<SB, NT>>>(h_self, W_self, W_neigh, out);
}